// round 14
// baseline (speedup 1.0000x reference)
#include <cuda_runtime.h>
#include <math.h>

#define T_TOK 512
#define CHUNK 64
#define NCHUNK 8
#define HH 28
#define WW 28
#define CC 4
#define DM 3136
#define DH 512

#define FSEG 196   // fwd/dadh split-K segments (k = 16 each)
#define PSEG 32    // pred split-K segments (k = 16 each)
#define GSEG 8     // kgram split-K segments (k = 392 each)

typedef unsigned long long ull;

// ---------------- f32x2 helpers ----------------
__device__ __forceinline__ ull pk2(float lo, float hi) {
    ull r; asm("mov.b64 %0, {%1,%2};" : "=l"(r) : "f"(lo), "f"(hi)); return r;
}
__device__ __forceinline__ void upk2(float& lo, float& hi, ull v) {
    asm("mov.b64 {%0,%1}, %2;" : "=f"(lo), "=f"(hi) : "l"(v));
}
#define FFMA2(d, a, b) asm("fma.rn.f32x2 %0, %1, %2, %0;" : "+l"(d) : "l"(a), "l"(b))
#define ADDX2(d, a)    asm("add.rn.f32x2 %0, %0, %1;" : "+l"(d) : "l"(a))

// ---------------- device scratch ----------------
__device__ __align__(16) float g_nk[T_TOK * DM];
__device__ __align__(16) float g_nv[T_TOK * DM];
__device__ __align__(16) float g_W1[DM * DH];
__device__ __align__(16) float g_W2[DH * DM];
__device__ __align__(16) float g_b1[DH];
__device__ __align__(16) float g_b2[DM];
__device__ __align__(16) float g_H[CHUNK * DH];
__device__ __align__(16) float g_A[CHUNK * DH];
__device__ __align__(16) float g_A2[CHUNK * DH];
__device__ __align__(16) float g_dpred[CHUNK * DM];
__device__ __align__(16) float g_dh[CHUNK * DH];
__device__ __align__(16) float g_G[CHUNK * CHUNK];
__device__ __align__(16) float g_fpart[FSEG * CHUNK * DH];    // 25.7 MB (fwd & dadh partials)
__device__ __align__(16) float g_ppart[PSEG * CHUNK * DM];    // 25.7 MB (pred/recall partials)
__device__ __align__(16) float g_gpart[GSEG * CHUNK * CHUNK];

// ---------------- math helpers ----------------
__device__ __forceinline__ float gelu_f(float x) {
    const float c = 0.7978845608028654f, a = 0.044715f;
    float u = c * (x + a * x * x * x);
    return 0.5f * x * (1.0f + tanhf(u));
}
__device__ __forceinline__ float dgelu_f(float x) {
    const float c = 0.7978845608028654f, a = 0.044715f;
    float x2 = x * x;
    float u = c * (x + a * x * x2);
    float th = tanhf(u);
    return 0.5f * (1.0f + th) + 0.5f * x * (1.0f - th * th) * c * (1.0f + 3.0f * a * x2);
}

// ---------------- prologue: conv3x3+rmsnorm and param copy ----------------
__global__ void prologue_kernel(const float* __restrict__ x,
                                const float* __restrict__ wk, const float* __restrict__ bk,
                                const float* __restrict__ wv, const float* __restrict__ bv,
                                const float* __restrict__ sk, const float* __restrict__ sv,
                                const float* __restrict__ W1, const float* __restrict__ b1,
                                const float* __restrict__ W2, const float* __restrict__ b2) {
    int tid = threadIdx.x;
    if (blockIdx.x < 1568) {
        __shared__ float swk[144], swv[144], sbk[4], sbv[4], ssk[4], ssv[4];
        if (tid < 144) { swk[tid] = wk[tid]; swv[tid] = wv[tid]; }
        if (tid < 4) { sbk[tid] = bk[tid]; sbv[tid] = bv[tid]; ssk[tid] = sk[tid]; ssv[tid] = sv[tid]; }
        __syncthreads();
        int idx = blockIdx.x * 256 + tid;   // 401408 exact
        int w = idx % WW;
        int h = (idx / WW) % HH;
        int t = idx / (HH * WW);
        float acck[4], accv[4];
#pragma unroll
        for (int o = 0; o < 4; o++) { acck[o] = sbk[o]; accv[o] = sbv[o]; }
        const float* xt = x + t * (CC * HH * WW);
#pragma unroll
        for (int kh = 0; kh < 3; kh++) {
            int hy = h + kh - 1;
            if (hy < 0 || hy >= HH) continue;
#pragma unroll
            for (int kw = 0; kw < 3; kw++) {
                int wx = w + kw - 1;
                if (wx < 0 || wx >= WW) continue;
                int wbase = (kh * 3 + kw) * 16;
#pragma unroll
                for (int ci = 0; ci < 4; ci++) {
                    float xv = xt[ci * (HH * WW) + hy * WW + wx];
#pragma unroll
                    for (int o = 0; o < 4; o++) {
                        acck[o] += xv * swk[wbase + ci * 4 + o];
                        accv[o] += xv * swv[wbase + ci * 4 + o];
                    }
                }
            }
        }
        float msk = 0.f, msv = 0.f;
#pragma unroll
        for (int o = 0; o < 4; o++) { msk += acck[o] * acck[o]; msv += accv[o] * accv[o]; }
        float ik = rsqrtf(msk * 0.25f + 1e-6f);
        float iv = rsqrtf(msv * 0.25f + 1e-6f);
        int base = t * DM + (h * WW + w) * CC;
#pragma unroll
        for (int o = 0; o < 4; o++) {
            g_nk[base + o] = acck[o] * ik * ssk[o];
            g_nv[base + o] = accv[o] * iv * ssv[o];
        }
    } else {
        int i = (blockIdx.x - 1568) * 256 + tid;   // 131072 threads
        for (int k = i; k < DM * DH; k += 131072) { g_W1[k] = W1[k]; g_W2[k] = W2[k]; }
        if (i < DH) g_b1[i] = b1[i];
        if (i < DM) g_b2[i] = b2[i];
    }
}

// ---------------- GEMM tile body (64m x 64n x 16k, 128 thr, 8m x 4n/thread) ----------------
__device__ __forceinline__ void gemm_body(
    const float* __restrict__ A, const float* __restrict__ B, float* __restrict__ C,
    int bx, int ntiles, int lda, int ldb, int ntot, int transb,
    float (&sA)[16][68], float (&sB)[16][68])
{
    int tid = threadIdx.x;
    int nt = bx % ntiles;
    int seg = bx / ntiles;
    int n0g = nt * 64;
    int k0 = seg * 16;

    // load A (64m x 16k) transposed -> sA[k][m]  (m contiguous)
#pragma unroll
    for (int i = tid; i < 256; i += 128) {
        int m = i >> 2;
        int f4 = (i & 3) * 4;
        float4 v = *reinterpret_cast<const float4*>(A + (size_t)m * lda + k0 + f4);
        sA[f4][m] = v.x; sA[f4 + 1][m] = v.y; sA[f4 + 2][m] = v.z; sA[f4 + 3][m] = v.w;
    }
    // load B tile (16k x 64n) -> sB[k][n]
    if (!transb) {
#pragma unroll
        for (int i = tid; i < 256; i += 128) {
            int k = i >> 4;
            int n4 = (i & 15) * 4;
            float4 v = *reinterpret_cast<const float4*>(B + (size_t)(k0 + k) * ldb + n0g + n4);
            *reinterpret_cast<float4*>(&sB[k][n4]) = v;
        }
    } else {
#pragma unroll
        for (int i = tid; i < 256; i += 128) {
            int n = i >> 2;
            int f4 = (i & 3) * 4;
            float4 v = *reinterpret_cast<const float4*>(B + (size_t)(n0g + n) * ldb + k0 + f4);
            sB[f4][n] = v.x; sB[f4 + 1][n] = v.y; sB[f4 + 2][n] = v.z; sB[f4 + 3][n] = v.w;
        }
    }
    __syncthreads();

    int m0 = (tid >> 4) * 8;
    int n0 = (tid & 15) * 4;
    ull acc[4][4];
#pragma unroll
    for (int i = 0; i < 4; i++)
#pragma unroll
        for (int j = 0; j < 4; j++) acc[i][j] = 0ULL;

#pragma unroll
    for (int kk = 0; kk < 16; kk++) {
        ulonglong2 alo = *reinterpret_cast<const ulonglong2*>(&sA[kk][m0]);
        ulonglong2 ahi = *reinterpret_cast<const ulonglong2*>(&sA[kk][m0 + 4]);
        float4 b = *reinterpret_cast<const float4*>(&sB[kk][n0]);
        ull b0 = pk2(b.x, b.x), b1 = pk2(b.y, b.y), b2 = pk2(b.z, b.z), b3 = pk2(b.w, b.w);
        FFMA2(acc[0][0], alo.x, b0); FFMA2(acc[0][1], alo.x, b1);
        FFMA2(acc[0][2], alo.x, b2); FFMA2(acc[0][3], alo.x, b3);
        FFMA2(acc[1][0], alo.y, b0); FFMA2(acc[1][1], alo.y, b1);
        FFMA2(acc[1][2], alo.y, b2); FFMA2(acc[1][3], alo.y, b3);
        FFMA2(acc[2][0], ahi.x, b0); FFMA2(acc[2][1], ahi.x, b1);
        FFMA2(acc[2][2], ahi.x, b2); FFMA2(acc[2][3], ahi.x, b3);
        FFMA2(acc[3][0], ahi.y, b0); FFMA2(acc[3][1], ahi.y, b1);
        FFMA2(acc[3][2], ahi.y, b2); FFMA2(acc[3][3], ahi.y, b3);
    }
    float* P = C + (size_t)seg * (64 * (size_t)ntot) + (size_t)m0 * ntot + n0g + n0;
#pragma unroll
    for (int mp = 0; mp < 4; mp++) {
        float e0, o0, e1, o1, e2, o2, e3, o3;
        upk2(e0, o0, acc[mp][0]); upk2(e1, o1, acc[mp][1]);
        upk2(e2, o2, acc[mp][2]); upk2(e3, o3, acc[mp][3]);
        *reinterpret_cast<float4*>(P + (size_t)(2 * mp) * ntot)     = make_float4(e0, e1, e2, e3);
        *reinterpret_cast<float4*>(P + (size_t)(2 * mp + 1) * ntot) = make_float4(o0, o1, o2, o3);
    }
}

// ---------------- stage1: fwd (K@W1) + kgram + prev-chunk recall pred (A2@W2) ----------------
// do_fwd: blocks [0,1568) fwd, [1568,1824) kgram, [1824,3392) recall (if do_recall)
// !do_fwd (epilogue): blocks [0,1568) recall
__global__ void __launch_bounds__(128) stage1_kernel(const float* __restrict__ Kc,
                                                     int do_fwd, int do_recall) {
    __shared__ float sA[16][68];
    __shared__ float sB[16][68];
    int bx = blockIdx.x;
    if (do_fwd) {
        if (bx < 1568) {
            gemm_body(Kc, g_W1, g_fpart, bx, 8, DM, DH, DH, 0, sA, sB);
            return;
        }
        if (bx < 1824) {
            int t = (bx - 1568) * 128 + threadIdx.x;   // 32768
            int gseg = t >> 12;
            int o = t & 4095;
            int m = o >> 6;
            int n = o & 63;
            int kbase = gseg * 392;
            const ull* pa = reinterpret_cast<const ull*>(Kc + (size_t)m * DM + kbase);
            const ull* pb = reinterpret_cast<const ull*>(Kc + (size_t)n * DM + kbase);
            ull acc2 = 0ULL;
#pragma unroll 8
            for (int k2 = 0; k2 < 196; k2++) FFMA2(acc2, pa[k2], pb[k2]);
            float lo, hi;
            upk2(lo, hi, acc2);
            g_gpart[gseg * 4096 + o] = lo + hi;
            return;
        }
        if (do_recall)
            gemm_body(g_A2, g_W2, g_ppart, bx - 1824, 49, DH, DM, DM, 0, sA, sB);
    } else {
        gemm_body(g_A2, g_W2, g_ppart, bx, 49, DH, DM, DM, 0, sA, sB);
    }
}

// ---------------- stage2: reduce fwd partials -> H,A ; G ; prev-chunk out-write ----------------
// do_main: blocks [0,512) H/A, [512,528) G, out region at 528; else out region at 0
__global__ void __launch_bounds__(256) stage2_kernel(int do_main, int do_out, int c_out,
                                                     float* __restrict__ out) {
    int bx = blockIdx.x;
    int obase = do_main ? 528 : 0;
    if (do_main && bx < 512) {
        __shared__ float red[256];
        int tid = threadIdx.x;
        int slice = tid >> 6;
        int o = tid & 63;
        int idx = bx * 64 + o;
        float s = 0.f;
        int s0 = slice * 49;
        const float* P = g_fpart + idx;
#pragma unroll 7
        for (int sg = 0; sg < 49; sg++)
            s += P[(s0 + sg) * (CHUNK * DH)];
        red[tid] = s;
        __syncthreads();
        if (slice == 0) {
            float t = red[o] + red[64 + o] + red[128 + o] + red[192 + o] + g_b1[idx & (DH - 1)];
            g_H[idx] = t;
            g_A[idx] = gelu_f(t);
        }
    } else if (do_main && bx < 528) {
        int t = (bx - 512) * 256 + threadIdx.x;
        float s = 0.f;
#pragma unroll
        for (int sg = 0; sg < GSEG; sg++) s += g_gpart[sg * 4096 + t];
        g_G[t] = s;
    } else if (do_out) {
        int f = (bx - obase) * 256 + threadIdx.x;   // 196 blocks = 50176
        int idx4 = f * 4;
        int d0 = idx4 % DM;
        ulonglong2 s = *reinterpret_cast<const ulonglong2*>(&g_b2[d0]);
#pragma unroll
        for (int sg = 0; sg < PSEG; sg++) {
            ulonglong2 p = *reinterpret_cast<const ulonglong2*>(&g_ppart[sg * (CHUNK * DM) + idx4]);
            ADDX2(s.x, p.x);
            ADDX2(s.y, p.y);
        }
        float s0, s1, s2, s3;
        upk2(s0, s1, s.x); upk2(s2, s3, s.y);
        *reinterpret_cast<float4*>(&out[c_out * (CHUNK * DM) + idx4]) = make_float4(s0, s1, s2, s3);
    }
}

// ---------------- pred GEMM: A@W2 -> ppart ----------------
__global__ void __launch_bounds__(128) pred_gemm_kernel(const float* __restrict__ Asrc) {
    __shared__ float sA[16][68];
    __shared__ float sB[16][68];
    gemm_body(Asrc, g_W2, g_ppart, blockIdx.x, 49, DH, DM, DM, 0, sA, sB);
}

// ---------------- dadh GEMM: dpred@W2^T -> fpart ----------------
__global__ void __launch_bounds__(128) dadh_gemm_kernel() {
    __shared__ float sA[16][68];
    __shared__ float sB[16][68];
    gemm_body(g_dpred, g_W2, g_fpart, blockIdx.x, 8, DM, DM, DH, 1, sA, sB);
}

// ---------------- reduce pred partials -> dpred ----------------
__global__ void __launch_bounds__(256) reduce2_kernel(int c) {
    int f = blockIdx.x * 256 + threadIdx.x;    // 196 blocks = 50176
    int idx4 = f * 4;
    int d0 = idx4 % DM;
    ulonglong2 s = *reinterpret_cast<const ulonglong2*>(&g_b2[d0]);
#pragma unroll
    for (int sg = 0; sg < PSEG; sg++) {
        ulonglong2 p = *reinterpret_cast<const ulonglong2*>(&g_ppart[sg * (CHUNK * DM) + idx4]);
        ADDX2(s.x, p.x);
        ADDX2(s.y, p.y);
    }
    float s0, s1, s2, s3;
    upk2(s0, s1, s.x); upk2(s2, s3, s.y);
    float4 v = *reinterpret_cast<const float4*>(&g_nv[c * (CHUNK * DM) + idx4]);
    *reinterpret_cast<float4*>(&g_dpred[idx4]) =
        make_float4(2.f * (s0 - v.x), 2.f * (s1 - v.y), 2.f * (s2 - v.z), 2.f * (s3 - v.w));
}

// ---------------- reduce dadh partials -> dh (4-way sliced, with dgelu) ----------------
__global__ void __launch_bounds__(256) reduceDh_kernel() {
    __shared__ float red[256];
    int tid = threadIdx.x;
    int slice = tid >> 6;
    int o = tid & 63;
    int idx = blockIdx.x * 64 + o;     // 512 blocks -> 32768 outputs
    float s = 0.f;
    int s0 = slice * 49;
    const float* P = g_fpart + idx;
#pragma unroll 7
    for (int sg = 0; sg < 49; sg++)
        s += P[(s0 + sg) * (CHUNK * DH)];
    red[tid] = s;
    __syncthreads();
    if (slice == 0) {
        float t = red[o] + red[64 + o] + red[128 + o] + red[192 + o];
        g_dh[idx] = t * dgelu_f(g_H[idx]);
    }
}

// ---------------- fused smem-tiled updates + recall activation (128 thr) ----------------
// [0,392):      W2 -= w * A^T @ dpred   (8 j-tiles x 49 d-tiles)
// [392,784):    W1 -= w * K^T @ dh      (49 k-tiles x 8 j-tiles)
// [784,1040):   A2 = gelu(H - w*(G@dh + colsum(dh)))
// [1040,1069):  biases
__global__ void __launch_bounds__(128) update_recall_kernel(const float* __restrict__ Kc, float wgt) {
    __shared__ float sU[64][68];
    __shared__ float sV[64][68];
    int tid = threadIdx.x;
    int bx = blockIdx.x;
    if (bx < 784) {
        const float* Asrc;  int alda;
        const float* Bsrc;  int blda;
        float* W;           int wld;
        int r0, c0;
        if (bx < 392) {
            int jt = bx / 49, dt = bx % 49;
            r0 = jt * 64; c0 = dt * 64;
            Asrc = g_A;     alda = DH;
            Bsrc = g_dpred; blda = DM;
            W = g_W2; wld = DM;
        } else {
            int b = bx - 392;
            int kt = b / 8, jt = b % 8;
            r0 = kt * 64; c0 = jt * 64;
            Asrc = Kc;   alda = DM;
            Bsrc = g_dh; blda = DH;
            W = g_W1; wld = DH;
        }
#pragma unroll
        for (int i = tid; i < 1024; i += 128) {
            int m = i >> 4;
            int r4 = (i & 15) * 4;
            float4 u = *reinterpret_cast<const float4*>(Asrc + (size_t)m * alda + r0 + r4);
            *reinterpret_cast<float4*>(&sU[m][r4]) = u;
            float4 v = *reinterpret_cast<const float4*>(Bsrc + (size_t)m * blda + c0 + r4);
            *reinterpret_cast<float4*>(&sV[m][r4]) = v;
        }
        __syncthreads();
        int rt = (tid >> 4) * 8;
        int ct = (tid & 15) * 4;
        ull acc[4][4];
#pragma unroll
        for (int i = 0; i < 4; i++)
#pragma unroll
            for (int j = 0; j < 4; j++) acc[i][j] = 0ULL;
#pragma unroll 8
        for (int m = 0; m < 64; m++) {
            ulonglong2 alo = *reinterpret_cast<const ulonglong2*>(&sU[m][rt]);
            ulonglong2 ahi = *reinterpret_cast<const ulonglong2*>(&sU[m][rt + 4]);
            float4 b = *reinterpret_cast<const float4*>(&sV[m][ct]);
            ull b0 = pk2(b.x, b.x), b1 = pk2(b.y, b.y), b2 = pk2(b.z, b.z), b3 = pk2(b.w, b.w);
            FFMA2(acc[0][0], alo.x, b0); FFMA2(acc[0][1], alo.x, b1);
            FFMA2(acc[0][2], alo.x, b2); FFMA2(acc[0][3], alo.x, b3);
            FFMA2(acc[1][0], alo.y, b0); FFMA2(acc[1][1], alo.y, b1);
            FFMA2(acc[1][2], alo.y, b2); FFMA2(acc[1][3], alo.y, b3);
            FFMA2(acc[2][0], ahi.x, b0); FFMA2(acc[2][1], ahi.x, b1);
            FFMA2(acc[2][2], ahi.x, b2); FFMA2(acc[2][3], ahi.x, b3);
            FFMA2(acc[3][0], ahi.y, b0); FFMA2(acc[3][1], ahi.y, b1);
            FFMA2(acc[3][2], ahi.y, b2); FFMA2(acc[3][3], ahi.y, b3);
        }
#pragma unroll
        for (int mp = 0; mp < 4; mp++) {
            float e0, o0, e1, o1, e2, o2, e3, o3;
            upk2(e0, o0, acc[mp][0]); upk2(e1, o1, acc[mp][1]);
            upk2(e2, o2, acc[mp][2]); upk2(e3, o3, acc[mp][3]);
            float* We = W + (size_t)(r0 + rt + 2 * mp) * wld + c0 + ct;
            float4 olde = *reinterpret_cast<float4*>(We);
            olde.x -= wgt * e0; olde.y -= wgt * e1; olde.z -= wgt * e2; olde.w -= wgt * e3;
            *reinterpret_cast<float4*>(We) = olde;
            float* Wo = W + (size_t)(r0 + rt + 2 * mp + 1) * wld + c0 + ct;
            float4 oldo = *reinterpret_cast<float4*>(Wo);
            oldo.x -= wgt * o0; oldo.y -= wgt * o1; oldo.z -= wgt * o2; oldo.w -= wgt * o3;
            *reinterpret_cast<float4*>(Wo) = oldo;
        }
    } else if (bx < 1040) {
        int e = (bx - 784) * 128 + tid;    // 32768
        int m = e >> 9;
        int j = e & (DH - 1);
        float s = 0.f, cs = 0.f;
        const float* Gm = g_G + m * CHUNK;
#pragma unroll 8
        for (int mp = 0; mp < CHUNK; mp++) {
            float d = g_dh[mp * DH + j];
            s += Gm[mp] * d;
            cs += d;
        }
        float H2 = g_H[e] - wgt * (s + cs);
        g_A2[e] = gelu_f(H2);
    } else {
        int i = (bx - 1040) * 128 + tid;   // 3712 >= 3648
        if (i < DH) {
            float s = 0.f;
#pragma unroll 8
            for (int m = 0; m < CHUNK; m++) s += g_dh[m * DH + i];
            g_b1[i] -= wgt * s;
        } else if (i < DH + DM) {
            int d = i - DH;
            float s = 0.f;
#pragma unroll 8
            for (int m = 0; m < CHUNK; m++) s += g_dpred[m * DM + d];
            g_b2[d] -= wgt * s;
        }
    }
}

// ---------------- launch ----------------
extern "C" void kernel_launch(void* const* d_in, const int* in_sizes, int n_in,
                              void* d_out, int out_size) {
    const float* x   = (const float*)d_in[0];
    const float* ckw = (const float*)d_in[1];
    const float* ckb = (const float*)d_in[2];
    const float* cvw = (const float*)d_in[3];
    const float* cvb = (const float*)d_in[4];
    const float* rsk = (const float*)d_in[5];
    const float* rsv = (const float*)d_in[6];
    const float* W1  = (const float*)d_in[7];
    const float* b1  = (const float*)d_in[8];
    const float* W2  = (const float*)d_in[9];
    const float* b2  = (const float*)d_in[10];
    float* out = (float*)d_out;

    // weights[i] = eta0*alpha^i * alpha^(CHUNK-1)/alpha^i = const
    float wgt = (float)(0.1 * pow(0.9, 63.0));

    float* nk_base;  cudaGetSymbolAddress((void**)&nk_base, g_nk);
    float* a_base;   cudaGetSymbolAddress((void**)&a_base, g_A);

    prologue_kernel<<<2080, 256>>>(x, ckw, ckb, cvw, cvb, rsk, rsv, W1, b1, W2, b2);

    for (int c = 0; c < NCHUNK; c++) {
        const float* Kc_p = nk_base + c * (CHUNK * DM);
        int has_prev = (c > 0);
        // stage1: fwd_c + kgram_c + recall-pred_{c-1}
        stage1_kernel<<<has_prev ? 3392 : 1824, 128>>>(Kc_p, 1, has_prev);
        // stage2: reduce1G_c + out-write_{c-1}
        stage2_kernel<<<has_prev ? 724 : 528, 256>>>(1, has_prev, c - 1, out);
        // pred_c: A@W2
        pred_gemm_kernel<<<1568, 128>>>(a_base);
        reduce2_kernel<<<196, 256>>>(c);
        // dadh_c: dpred@W2^T
        dadh_gemm_kernel<<<1568, 128>>>();
        reduceDh_kernel<<<512, 256>>>();
        // update_c + A2_c (Gram recall)
        update_recall_kernel<<<1069, 128>>>(Kc_p, wgt);
    }
    // epilogue: recall-pred_7 + out-write_7
    stage1_kernel<<<1568, 128>>>(nk_base, 0, 1);
    stage2_kernel<<<196, 256>>>(0, 1, NCHUNK - 1, out);
}

// round 15
// speedup vs baseline: 1.1169x; 1.1169x over previous
#include <cuda_runtime.h>
#include <math.h>

#define T_TOK 512
#define CHUNK 64
#define NCHUNK 8
#define HH 28
#define WW 28
#define CC 4
#define DM 3136
#define DH 512

#define FSEG 98    // fwd/dadh split-K segments (k = 32 each)
#define PSEG 16    // pred split-K segments (k = 32 each)
#define GSEG 8     // kgram split-K segments (k = 392 each)

typedef unsigned long long ull;

// ---------------- f32x2 helpers ----------------
__device__ __forceinline__ ull pk2(float lo, float hi) {
    ull r; asm("mov.b64 %0, {%1,%2};" : "=l"(r) : "f"(lo), "f"(hi)); return r;
}
__device__ __forceinline__ void upk2(float& lo, float& hi, ull v) {
    asm("mov.b64 {%0,%1}, %2;" : "=f"(lo), "=f"(hi) : "l"(v));
}
#define FFMA2(d, a, b) asm("fma.rn.f32x2 %0, %1, %2, %0;" : "+l"(d) : "l"(a), "l"(b))
#define ADDX2(d, a)    asm("add.rn.f32x2 %0, %0, %1;" : "+l"(d) : "l"(a))

// ---------------- device scratch ----------------
__device__ __align__(16) float g_nk[T_TOK * DM];
__device__ __align__(16) float g_nv[T_TOK * DM];
__device__ __align__(16) float g_W1[DM * DH];
__device__ __align__(16) float g_W2[DH * DM];
__device__ __align__(16) float g_b1[DH];
__device__ __align__(16) float g_b2[DM];
__device__ __align__(16) float g_H[CHUNK * DH];
__device__ __align__(16) float g_A[CHUNK * DH];
__device__ __align__(16) float g_A2[CHUNK * DH];
__device__ __align__(16) float g_dpred[CHUNK * DM];
__device__ __align__(16) float g_dh[CHUNK * DH];
__device__ __align__(16) float g_G[CHUNK * CHUNK];
__device__ __align__(16) float g_fpart[FSEG * CHUNK * DH];    // 12.8 MB (fwd & dadh partials)
__device__ __align__(16) float g_ppart[PSEG * CHUNK * DM];    // 12.8 MB (pred/recall partials)
__device__ __align__(16) float g_gpart[GSEG * CHUNK * CHUNK];

// ---------------- math helpers ----------------
__device__ __forceinline__ float gelu_f(float x) {
    const float c = 0.7978845608028654f, a = 0.044715f;
    float u = c * (x + a * x * x * x);
    return 0.5f * x * (1.0f + tanhf(u));
}
__device__ __forceinline__ float dgelu_f(float x) {
    const float c = 0.7978845608028654f, a = 0.044715f;
    float x2 = x * x;
    float u = c * (x + a * x * x2);
    float th = tanhf(u);
    return 0.5f * (1.0f + th) + 0.5f * x * (1.0f - th * th) * c * (1.0f + 3.0f * a * x2);
}

// ---------------- prologue: conv3x3+rmsnorm and param copy ----------------
__global__ void prologue_kernel(const float* __restrict__ x,
                                const float* __restrict__ wk, const float* __restrict__ bk,
                                const float* __restrict__ wv, const float* __restrict__ bv,
                                const float* __restrict__ sk, const float* __restrict__ sv,
                                const float* __restrict__ W1, const float* __restrict__ b1,
                                const float* __restrict__ W2, const float* __restrict__ b2) {
    int tid = threadIdx.x;
    if (blockIdx.x < 1568) {
        __shared__ float swk[144], swv[144], sbk[4], sbv[4], ssk[4], ssv[4];
        if (tid < 144) { swk[tid] = wk[tid]; swv[tid] = wv[tid]; }
        if (tid < 4) { sbk[tid] = bk[tid]; sbv[tid] = bv[tid]; ssk[tid] = sk[tid]; ssv[tid] = sv[tid]; }
        __syncthreads();
        int idx = blockIdx.x * 256 + tid;   // 401408 exact
        int w = idx % WW;
        int h = (idx / WW) % HH;
        int t = idx / (HH * WW);
        float acck[4], accv[4];
#pragma unroll
        for (int o = 0; o < 4; o++) { acck[o] = sbk[o]; accv[o] = sbv[o]; }
        const float* xt = x + t * (CC * HH * WW);
#pragma unroll
        for (int kh = 0; kh < 3; kh++) {
            int hy = h + kh - 1;
            if (hy < 0 || hy >= HH) continue;
#pragma unroll
            for (int kw = 0; kw < 3; kw++) {
                int wx = w + kw - 1;
                if (wx < 0 || wx >= WW) continue;
                int wbase = (kh * 3 + kw) * 16;
#pragma unroll
                for (int ci = 0; ci < 4; ci++) {
                    float xv = xt[ci * (HH * WW) + hy * WW + wx];
#pragma unroll
                    for (int o = 0; o < 4; o++) {
                        acck[o] += xv * swk[wbase + ci * 4 + o];
                        accv[o] += xv * swv[wbase + ci * 4 + o];
                    }
                }
            }
        }
        float msk = 0.f, msv = 0.f;
#pragma unroll
        for (int o = 0; o < 4; o++) { msk += acck[o] * acck[o]; msv += accv[o] * accv[o]; }
        float ik = rsqrtf(msk * 0.25f + 1e-6f);
        float iv = rsqrtf(msv * 0.25f + 1e-6f);
        int base = t * DM + (h * WW + w) * CC;
#pragma unroll
        for (int o = 0; o < 4; o++) {
            g_nk[base + o] = acck[o] * ik * ssk[o];
            g_nv[base + o] = accv[o] * iv * ssv[o];
        }
    } else {
        int i = (blockIdx.x - 1568) * 256 + tid;   // 131072 threads
        for (int k = i; k < DM * DH; k += 131072) { g_W1[k] = W1[k]; g_W2[k] = W2[k]; }
        if (i < DH) g_b1[i] = b1[i];
        if (i < DM) g_b2[i] = b2[i];
    }
}

// ---------------- GEMM tile body (64m x 64n x 32k, 128 thr, 8m x 4n/thread) ----------------
// 4-stage software pipeline: all LDGs issued up-front (MLP=8); smem stores + compute
// of stage s overlap in-flight latency of later stages. k-ascending order preserved.
__device__ __forceinline__ void gemm_body(
    const float* __restrict__ A, const float* __restrict__ B, float* __restrict__ C,
    int bx, int ntiles, int lda, int ldb, int ntot, int transb,
    float (&sA)[32][68], float (&sB)[32][68])
{
    int tid = threadIdx.x;
    int nt = bx % ntiles;
    int seg = bx / ntiles;
    int n0g = nt * 64;
    int k0 = seg * 32;

    int am  = tid >> 3;            // 0..15 (row base for A / transb-B loads)
    int af4 = (tid & 7) * 4;       // k-offset 0..28
    int astage = (tid & 7) >> 1;   // stage owning this thread's A (and transb-B) data

    // A loads: 4 float4, rows am+16t, cols k0+af4..+3
    float4 aR[4];
#pragma unroll
    for (int t = 0; t < 4; t++)
        aR[t] = *reinterpret_cast<const float4*>(A + (size_t)(am + 16 * t) * lda + k0 + af4);

    // B loads
    float4 bR[4];
    int bk = tid >> 4;             // 0..7
    int bn4 = (tid & 15) * 4;
    if (!transb) {
#pragma unroll
        for (int t = 0; t < 4; t++)
            bR[t] = *reinterpret_cast<const float4*>(B + (size_t)(k0 + bk + 8 * t) * ldb + n0g + bn4);
    } else {
#pragma unroll
        for (int t = 0; t < 4; t++)
            bR[t] = *reinterpret_cast<const float4*>(B + (size_t)(n0g + am + 16 * t) * ldb + k0 + af4);
    }

    int m0 = (tid >> 4) * 8;
    int n0 = (tid & 15) * 4;
    ull acc[4][4];
#pragma unroll
    for (int i = 0; i < 4; i++)
#pragma unroll
        for (int j = 0; j < 4; j++) acc[i][j] = 0ULL;

    // ---- stage 0 stores ----
    if (astage == 0) {
#pragma unroll
        for (int t = 0; t < 4; t++) {
            int mm = am + 16 * t;
            sA[af4][mm] = aR[t].x; sA[af4 + 1][mm] = aR[t].y;
            sA[af4 + 2][mm] = aR[t].z; sA[af4 + 3][mm] = aR[t].w;
            if (transb) {
                sB[af4][mm] = bR[t].x; sB[af4 + 1][mm] = bR[t].y;
                sB[af4 + 2][mm] = bR[t].z; sB[af4 + 3][mm] = bR[t].w;
            }
        }
    }
    if (!transb)
        *reinterpret_cast<float4*>(&sB[bk][bn4]) = bR[0];
    __syncthreads();

#pragma unroll
    for (int s = 0; s < 4; s++) {
        if (s < 3) {
            int sn = s + 1;
            if (astage == sn) {
#pragma unroll
                for (int t = 0; t < 4; t++) {
                    int mm = am + 16 * t;
                    sA[af4][mm] = aR[t].x; sA[af4 + 1][mm] = aR[t].y;
                    sA[af4 + 2][mm] = aR[t].z; sA[af4 + 3][mm] = aR[t].w;
                    if (transb) {
                        sB[af4][mm] = bR[t].x; sB[af4 + 1][mm] = bR[t].y;
                        sB[af4 + 2][mm] = bR[t].z; sB[af4 + 3][mm] = bR[t].w;
                    }
                }
            }
            if (!transb)
                *reinterpret_cast<float4*>(&sB[bk + 8 * sn][bn4]) = bR[sn];
        }
#pragma unroll
        for (int kk = 8 * s; kk < 8 * s + 8; kk++) {
            ulonglong2 alo = *reinterpret_cast<const ulonglong2*>(&sA[kk][m0]);
            ulonglong2 ahi = *reinterpret_cast<const ulonglong2*>(&sA[kk][m0 + 4]);
            float4 b = *reinterpret_cast<const float4*>(&sB[kk][n0]);
            ull b0 = pk2(b.x, b.x), b1 = pk2(b.y, b.y), b2 = pk2(b.z, b.z), b3 = pk2(b.w, b.w);
            FFMA2(acc[0][0], alo.x, b0); FFMA2(acc[0][1], alo.x, b1);
            FFMA2(acc[0][2], alo.x, b2); FFMA2(acc[0][3], alo.x, b3);
            FFMA2(acc[1][0], alo.y, b0); FFMA2(acc[1][1], alo.y, b1);
            FFMA2(acc[1][2], alo.y, b2); FFMA2(acc[1][3], alo.y, b3);
            FFMA2(acc[2][0], ahi.x, b0); FFMA2(acc[2][1], ahi.x, b1);
            FFMA2(acc[2][2], ahi.x, b2); FFMA2(acc[2][3], ahi.x, b3);
            FFMA2(acc[3][0], ahi.y, b0); FFMA2(acc[3][1], ahi.y, b1);
            FFMA2(acc[3][2], ahi.y, b2); FFMA2(acc[3][3], ahi.y, b3);
        }
        if (s < 3) __syncthreads();
    }

    float* P = C + (size_t)seg * (64 * (size_t)ntot) + (size_t)m0 * ntot + n0g + n0;
#pragma unroll
    for (int mp = 0; mp < 4; mp++) {
        float e0, o0, e1, o1, e2, o2, e3, o3;
        upk2(e0, o0, acc[mp][0]); upk2(e1, o1, acc[mp][1]);
        upk2(e2, o2, acc[mp][2]); upk2(e3, o3, acc[mp][3]);
        *reinterpret_cast<float4*>(P + (size_t)(2 * mp) * ntot)     = make_float4(e0, e1, e2, e3);
        *reinterpret_cast<float4*>(P + (size_t)(2 * mp + 1) * ntot) = make_float4(o0, o1, o2, o3);
    }
}

// ---------------- stage1: fwd (K@W1) + kgram + prev-chunk recall pred (A2@W2) ----------------
// do_fwd: blocks [0,784) fwd, [784,1040) kgram, [1040,1824) recall (if do_recall)
// !do_fwd (epilogue): blocks [0,784) recall
__global__ void __launch_bounds__(128) stage1_kernel(const float* __restrict__ Kc,
                                                     int do_fwd, int do_recall) {
    __shared__ float sA[32][68];
    __shared__ float sB[32][68];
    int bx = blockIdx.x;
    if (do_fwd) {
        if (bx < 784) {
            gemm_body(Kc, g_W1, g_fpart, bx, 8, DM, DH, DH, 0, sA, sB);
            return;
        }
        if (bx < 1040) {
            int t = (bx - 784) * 128 + threadIdx.x;   // 32768
            int gseg = t >> 12;
            int o = t & 4095;
            int m = o >> 6;
            int n = o & 63;
            int kbase = gseg * 392;
            const ull* pa = reinterpret_cast<const ull*>(Kc + (size_t)m * DM + kbase);
            const ull* pb = reinterpret_cast<const ull*>(Kc + (size_t)n * DM + kbase);
            ull acc2 = 0ULL;
#pragma unroll 8
            for (int k2 = 0; k2 < 196; k2++) FFMA2(acc2, pa[k2], pb[k2]);
            float lo, hi;
            upk2(lo, hi, acc2);
            g_gpart[gseg * 4096 + o] = lo + hi;
            return;
        }
        if (do_recall)
            gemm_body(g_A2, g_W2, g_ppart, bx - 1040, 49, DH, DM, DM, 0, sA, sB);
    } else {
        gemm_body(g_A2, g_W2, g_ppart, bx, 49, DH, DM, DM, 0, sA, sB);
    }
}

// ---------------- stage2: reduce fwd partials -> H,A ; G ; prev-chunk out-write ----------------
__global__ void __launch_bounds__(256) stage2_kernel(int do_main, int do_out, int c_out,
                                                     float* __restrict__ out) {
    int bx = blockIdx.x;
    int obase = do_main ? 528 : 0;
    if (do_main && bx < 512) {
        __shared__ float red[256];
        int tid = threadIdx.x;
        int slice = tid >> 6;
        int o = tid & 63;
        int idx = bx * 64 + o;
        const int start[4] = {0, 25, 50, 74};
        const int cnt[4] = {25, 25, 24, 24};
        float s = 0.f;
        int s0 = start[slice], n = cnt[slice];
        const float* P = g_fpart + idx;
#pragma unroll 5
        for (int sg = 0; sg < n; sg++)
            s += P[(s0 + sg) * (CHUNK * DH)];
        red[tid] = s;
        __syncthreads();
        if (slice == 0) {
            float t = red[o] + red[64 + o] + red[128 + o] + red[192 + o] + g_b1[idx & (DH - 1)];
            g_H[idx] = t;
            g_A[idx] = gelu_f(t);
        }
    } else if (do_main && bx < 528) {
        int t = (bx - 512) * 256 + threadIdx.x;
        float s = 0.f;
#pragma unroll
        for (int sg = 0; sg < GSEG; sg++) s += g_gpart[sg * 4096 + t];
        g_G[t] = s;
    } else if (do_out) {
        int f = (bx - obase) * 256 + threadIdx.x;   // 196 blocks = 50176
        int idx4 = f * 4;
        int d0 = idx4 % DM;
        ulonglong2 s = *reinterpret_cast<const ulonglong2*>(&g_b2[d0]);
#pragma unroll
        for (int sg = 0; sg < PSEG; sg++) {
            ulonglong2 p = *reinterpret_cast<const ulonglong2*>(&g_ppart[sg * (CHUNK * DM) + idx4]);
            ADDX2(s.x, p.x);
            ADDX2(s.y, p.y);
        }
        float s0, s1, s2, s3;
        upk2(s0, s1, s.x); upk2(s2, s3, s.y);
        *reinterpret_cast<float4*>(&out[c_out * (CHUNK * DM) + idx4]) = make_float4(s0, s1, s2, s3);
    }
}

// ---------------- pred GEMM: A@W2 -> ppart ----------------
__global__ void __launch_bounds__(128) pred_gemm_kernel(const float* __restrict__ Asrc) {
    __shared__ float sA[32][68];
    __shared__ float sB[32][68];
    gemm_body(Asrc, g_W2, g_ppart, blockIdx.x, 49, DH, DM, DM, 0, sA, sB);
}

// ---------------- dadh GEMM: dpred@W2^T -> fpart ----------------
__global__ void __launch_bounds__(128) dadh_gemm_kernel() {
    __shared__ float sA[32][68];
    __shared__ float sB[32][68];
    gemm_body(g_dpred, g_W2, g_fpart, blockIdx.x, 8, DM, DM, DH, 1, sA, sB);
}

// ---------------- reduce pred partials -> dpred ----------------
__global__ void __launch_bounds__(256) reduce2_kernel(int c) {
    int f = blockIdx.x * 256 + threadIdx.x;    // 196 blocks = 50176
    int idx4 = f * 4;
    int d0 = idx4 % DM;
    ulonglong2 s = *reinterpret_cast<const ulonglong2*>(&g_b2[d0]);
#pragma unroll
    for (int sg = 0; sg < PSEG; sg++) {
        ulonglong2 p = *reinterpret_cast<const ulonglong2*>(&g_ppart[sg * (CHUNK * DM) + idx4]);
        ADDX2(s.x, p.x);
        ADDX2(s.y, p.y);
    }
    float s0, s1, s2, s3;
    upk2(s0, s1, s.x); upk2(s2, s3, s.y);
    float4 v = *reinterpret_cast<const float4*>(&g_nv[c * (CHUNK * DM) + idx4]);
    *reinterpret_cast<float4*>(&g_dpred[idx4]) =
        make_float4(2.f * (s0 - v.x), 2.f * (s1 - v.y), 2.f * (s2 - v.z), 2.f * (s3 - v.w));
}

// ---------------- reduce dadh partials -> dh (4-way sliced, with dgelu) ----------------
__global__ void __launch_bounds__(256) reduceDh_kernel() {
    __shared__ float red[256];
    int tid = threadIdx.x;
    int slice = tid >> 6;
    int o = tid & 63;
    int idx = blockIdx.x * 64 + o;     // 512 blocks -> 32768 outputs
    const int start[4] = {0, 25, 50, 74};
    const int cnt[4] = {25, 25, 24, 24};
    float s = 0.f;
    int s0 = start[slice], n = cnt[slice];
    const float* P = g_fpart + idx;
#pragma unroll 5
    for (int sg = 0; sg < n; sg++)
        s += P[(s0 + sg) * (CHUNK * DH)];
    red[tid] = s;
    __syncthreads();
    if (slice == 0) {
        float t = red[o] + red[64 + o] + red[128 + o] + red[192 + o];
        g_dh[idx] = t * dgelu_f(g_H[idx]);
    }
}

// ---------------- fused smem-tiled updates + recall activation (128 thr) ----------------
// [0,392):      W2 -= w * A^T @ dpred   (8 j-tiles x 49 d-tiles)
// [392,784):    W1 -= w * K^T @ dh      (49 k-tiles x 8 j-tiles)
// [784,1040):   A2 = gelu(H - w*(G@dh + colsum(dh)))
// [1040,1069):  biases
__global__ void __launch_bounds__(128) update_recall_kernel(const float* __restrict__ Kc, float wgt) {
    __shared__ float sU[64][68];
    __shared__ float sV[64][68];
    int tid = threadIdx.x;
    int bx = blockIdx.x;
    if (bx < 784) {
        const float* Asrc;  int alda;
        const float* Bsrc;  int blda;
        float* W;           int wld;
        int r0, c0;
        if (bx < 392) {
            int jt = bx / 49, dt = bx % 49;
            r0 = jt * 64; c0 = dt * 64;
            Asrc = g_A;     alda = DH;
            Bsrc = g_dpred; blda = DM;
            W = g_W2; wld = DM;
        } else {
            int b = bx - 392;
            int kt = b / 8, jt = b % 8;
            r0 = kt * 64; c0 = jt * 64;
            Asrc = Kc;   alda = DM;
            Bsrc = g_dh; blda = DH;
            W = g_W1; wld = DH;
        }
        // 2-stage pipeline over m-halves. sU[m][r] = Asrc[m, r0+r], sV[m][cc] = Bsrc[m, c0+cc]
        int um = tid >> 4;             // 0..7
        int r4 = (tid & 15) * 4;
        float4 uR[4], vR[4];
#pragma unroll
        for (int t = 0; t < 4; t++) {
            uR[t] = *reinterpret_cast<const float4*>(Asrc + (size_t)(um + 8 * t) * alda + r0 + r4);
            vR[t] = *reinterpret_cast<const float4*>(Bsrc + (size_t)(um + 8 * t) * blda + c0 + r4);
        }
#pragma unroll
        for (int t = 0; t < 4; t++) {
            *reinterpret_cast<float4*>(&sU[um + 8 * t][r4]) = uR[t];
            *reinterpret_cast<float4*>(&sV[um + 8 * t][r4]) = vR[t];
        }
        // issue stage-2 loads (latency hidden under first-half compute)
#pragma unroll
        for (int t = 0; t < 4; t++) {
            uR[t] = *reinterpret_cast<const float4*>(Asrc + (size_t)(um + 32 + 8 * t) * alda + r0 + r4);
            vR[t] = *reinterpret_cast<const float4*>(Bsrc + (size_t)(um + 32 + 8 * t) * blda + c0 + r4);
        }
        __syncthreads();

        int rt = (tid >> 4) * 8;
        int ct = (tid & 15) * 4;
        ull acc[4][4];
#pragma unroll
        for (int i = 0; i < 4; i++)
#pragma unroll
            for (int j = 0; j < 4; j++) acc[i][j] = 0ULL;

#pragma unroll 8
        for (int m = 0; m < 32; m++) {
            ulonglong2 alo = *reinterpret_cast<const ulonglong2*>(&sU[m][rt]);
            ulonglong2 ahi = *reinterpret_cast<const ulonglong2*>(&sU[m][rt + 4]);
            float4 b = *reinterpret_cast<const float4*>(&sV[m][ct]);
            ull b0 = pk2(b.x, b.x), b1 = pk2(b.y, b.y), b2 = pk2(b.z, b.z), b3 = pk2(b.w, b.w);
            FFMA2(acc[0][0], alo.x, b0); FFMA2(acc[0][1], alo.x, b1);
            FFMA2(acc[0][2], alo.x, b2); FFMA2(acc[0][3], alo.x, b3);
            FFMA2(acc[1][0], alo.y, b0); FFMA2(acc[1][1], alo.y, b1);
            FFMA2(acc[1][2], alo.y, b2); FFMA2(acc[1][3], alo.y, b3);
            FFMA2(acc[2][0], ahi.x, b0); FFMA2(acc[2][1], ahi.x, b1);
            FFMA2(acc[2][2], ahi.x, b2); FFMA2(acc[2][3], ahi.x, b3);
            FFMA2(acc[3][0], ahi.y, b0); FFMA2(acc[3][1], ahi.y, b1);
            FFMA2(acc[3][2], ahi.y, b2); FFMA2(acc[3][3], ahi.y, b3);
        }
        // store stage 2
#pragma unroll
        for (int t = 0; t < 4; t++) {
            *reinterpret_cast<float4*>(&sU[um + 32 + 8 * t][r4]) = uR[t];
            *reinterpret_cast<float4*>(&sV[um + 32 + 8 * t][r4]) = vR[t];
        }
        __syncthreads();
#pragma unroll 8
        for (int m = 32; m < 64; m++) {
            ulonglong2 alo = *reinterpret_cast<const ulonglong2*>(&sU[m][rt]);
            ulonglong2 ahi = *reinterpret_cast<const ulonglong2*>(&sU[m][rt + 4]);
            float4 b = *reinterpret_cast<const float4*>(&sV[m][ct]);
            ull b0 = pk2(b.x, b.x), b1 = pk2(b.y, b.y), b2 = pk2(b.z, b.z), b3 = pk2(b.w, b.w);
            FFMA2(acc[0][0], alo.x, b0); FFMA2(acc[0][1], alo.x, b1);
            FFMA2(acc[0][2], alo.x, b2); FFMA2(acc[0][3], alo.x, b3);
            FFMA2(acc[1][0], alo.y, b0); FFMA2(acc[1][1], alo.y, b1);
            FFMA2(acc[1][2], alo.y, b2); FFMA2(acc[1][3], alo.y, b3);
            FFMA2(acc[2][0], ahi.x, b0); FFMA2(acc[2][1], ahi.x, b1);
            FFMA2(acc[2][2], ahi.x, b2); FFMA2(acc[2][3], ahi.x, b3);
            FFMA2(acc[3][0], ahi.y, b0); FFMA2(acc[3][1], ahi.y, b1);
            FFMA2(acc[3][2], ahi.y, b2); FFMA2(acc[3][3], ahi.y, b3);
        }

#pragma unroll
        for (int mp = 0; mp < 4; mp++) {
            float e0, o0, e1, o1, e2, o2, e3, o3;
            upk2(e0, o0, acc[mp][0]); upk2(e1, o1, acc[mp][1]);
            upk2(e2, o2, acc[mp][2]); upk2(e3, o3, acc[mp][3]);
            float* We = W + (size_t)(r0 + rt + 2 * mp) * wld + c0 + ct;
            float4 olde = *reinterpret_cast<float4*>(We);
            olde.x -= wgt * e0; olde.y -= wgt * e1; olde.z -= wgt * e2; olde.w -= wgt * e3;
            *reinterpret_cast<float4*>(We) = olde;
            float* Wo = W + (size_t)(r0 + rt + 2 * mp + 1) * wld + c0 + ct;
            float4 oldo = *reinterpret_cast<float4*>(Wo);
            oldo.x -= wgt * o0; oldo.y -= wgt * o1; oldo.z -= wgt * o2; oldo.w -= wgt * o3;
            *reinterpret_cast<float4*>(Wo) = oldo;
        }
    } else if (bx < 1040) {
        int e = (bx - 784) * 128 + tid;    // 32768
        int m = e >> 9;
        int j = e & (DH - 1);
        float s = 0.f, cs = 0.f;
        const float* Gm = g_G + m * CHUNK;
#pragma unroll 8
        for (int mp = 0; mp < CHUNK; mp++) {
            float d = g_dh[mp * DH + j];
            s += Gm[mp] * d;
            cs += d;
        }
        float H2 = g_H[e] - wgt * (s + cs);
        g_A2[e] = gelu_f(H2);
    } else {
        int i = (bx - 1040) * 128 + tid;   // 3712 >= 3648
        if (i < DH) {
            float s = 0.f;
#pragma unroll 8
            for (int m = 0; m < CHUNK; m++) s += g_dh[m * DH + i];
            g_b1[i] -= wgt * s;
        } else if (i < DH + DM) {
            int d = i - DH;
            float s = 0.f;
#pragma unroll 8
            for (int m = 0; m < CHUNK; m++) s += g_dpred[m * DM + d];
            g_b2[d] -= wgt * s;
        }
    }
}

// ---------------- launch ----------------
extern "C" void kernel_launch(void* const* d_in, const int* in_sizes, int n_in,
                              void* d_out, int out_size) {
    const float* x   = (const float*)d_in[0];
    const float* ckw = (const float*)d_in[1];
    const float* ckb = (const float*)d_in[2];
    const float* cvw = (const float*)d_in[3];
    const float* cvb = (const float*)d_in[4];
    const float* rsk = (const float*)d_in[5];
    const float* rsv = (const float*)d_in[6];
    const float* W1  = (const float*)d_in[7];
    const float* b1  = (const float*)d_in[8];
    const float* W2  = (const float*)d_in[9];
    const float* b2  = (const float*)d_in[10];
    float* out = (float*)d_out;

    // weights[i] = eta0*alpha^i * alpha^(CHUNK-1)/alpha^i = const
    float wgt = (float)(0.1 * pow(0.9, 63.0));

    float* nk_base;  cudaGetSymbolAddress((void**)&nk_base, g_nk);
    float* a_base;   cudaGetSymbolAddress((void**)&a_base, g_A);

    prologue_kernel<<<2080, 256>>>(x, ckw, ckb, cvw, cvb, rsk, rsv, W1, b1, W2, b2);

    for (int c = 0; c < NCHUNK; c++) {
        const float* Kc_p = nk_base + c * (CHUNK * DM);
        int has_prev = (c > 0);
        // stage1: fwd_c + kgram_c + recall-pred_{c-1}
        stage1_kernel<<<has_prev ? 1824 : 1040, 128>>>(Kc_p, 1, has_prev);
        // stage2: reduce1G_c + out-write_{c-1}
        stage2_kernel<<<has_prev ? 724 : 528, 256>>>(1, has_prev, c - 1, out);
        // pred_c: A@W2
        pred_gemm_kernel<<<784, 128>>>(a_base);
        reduce2_kernel<<<196, 256>>>(c);
        // dadh_c: dpred@W2^T
        dadh_gemm_kernel<<<784, 128>>>();
        reduceDh_kernel<<<512, 256>>>();
        // update_c + A2_c (Gram recall)
        update_recall_kernel<<<1069, 128>>>(Kc_p, wgt);
    }
    // epilogue: recall-pred_7 + out-write_7
    stage1_kernel<<<784, 128>>>(nk_base, 0, 1);
    stage2_kernel<<<196, 256>>>(0, 1, NCHUNK - 1, out);
}